// round 10
// baseline (speedup 1.0000x reference)
#include <cuda_runtime.h>

// Problem constants (fixed by the dataset): B=512, T=512, L=128
#define BB 512
#define TT 512
#define LL 128
#define NB 2                 // batches per CTA
#define NCTA (BB / NB)       // 256 CTAs, 2 co-resident per SM
#define PROW 136             // padded P row: cols 0-63 at [0,64), 64-127 at [68,132)
#define C128 0.0078125f      // 2^-7 : exact per-step rescale (ln128 == 7*ln2)
#define KFINAL 2474.5354346f // 510 steps * 7 * ln2

__device__ __forceinline__ unsigned long long pack2(float x, float y) {
    unsigned long long r;
    asm("mov.b64 %0, {%1, %2};" : "=l"(r) : "f"(x), "f"(y));
    return r;
}
__device__ __forceinline__ void unpack2(float& x, float& y, unsigned long long v) {
    asm("mov.b64 {%0, %1}, %2;" : "=f"(x), "=f"(y) : "l"(v));
}
__device__ __forceinline__ unsigned long long fma2(unsigned long long a,
                                                   unsigned long long b,
                                                   unsigned long long c) {
    unsigned long long d;
    asm("fma.rn.f32x2 %0, %1, %2, %3;" : "=l"(d) : "l"(a), "l"(b), "l"(c));
    return d;
}
__device__ __forceinline__ unsigned long long add2(unsigned long long a,
                                                   unsigned long long b) {
    unsigned long long d;
    asm("add.rn.f32x2 %0, %1, %2;" : "=l"(d) : "l"(a), "l"(b));
    return d;
}
__device__ __forceinline__ float hsum2(unsigned long long v) {
    float x, y;
    unpack2(x, y, v);
    return x + y;
}

// Persistent: one CTA = 2 batches, 2 CTAs/SM. 128 threads.
//   jj = w*16 + (l&15); ih = l>>4; owns cols jj & jj+64 over i-half 64*ih.
// STAGGERED step: the two batches are processed in alternating phases with
// their own barrier each, so every barrier's convoy/release is overlapped by
// ~300 cycles of the OTHER batch's dot-product work:
//   ... BAR_B | dot0 -> W0 -> STS P0' | BAR_A | dot1 -> W1 -> STS P1' | BAR_B ...
// Linear-domain recurrence with constant 2^-7 rescale (ln128 = 7 ln2 exactly):
// no log/exp/anchor on the critical path.
__global__ __launch_bounds__(128, 2) void crf_kernel(
    const float* __restrict__ feats,     // [B, T, L]
    const float* __restrict__ transfer,  // [L, L]
    const int*   __restrict__ target,    // [B, T]
    const int*   __restrict__ startp,    // scalar (may be null -> L-2)
    const int*   __restrict__ stopp,     // scalar (may be null -> L-1)
    float*       __restrict__ out)       // [B]
{
    __shared__ __align__(16) float Psh[2][NB][PROW];  // [buf][batch][padded row]
    __shared__ float smax[NB][4];
    __shared__ float ssum[NB][4];
    __shared__ float sg[NB][4];

    const int tid  = threadIdx.x;
    const int lane = tid & 31;
    const int wid  = tid >> 5;
    const int jj   = (wid << 4) + (lane & 15);
    const int ih   = lane >> 4;
    const int jown = jj + (ih << 6);
    const int fown = jj + ih * 68;
    const int b0   = blockIdx.x * NB;

    const int start = startp ? *startp : (LL - 2);
    const int stop  = stopp  ? *stopp  : (LL - 1);

    // ---- E tiles: i in [64*ih, 64*ih+64) for columns jj and jj+64 ----
    unsigned long long Ea[32], Eb[32];
    {
        const int i0 = ih << 6;
#pragma unroll
        for (int m = 0; m < 32; m++) {
            const int ia = i0 + 2 * m;
            Ea[m] = pack2(__expf(transfer[ia * LL + jj]),
                          __expf(transfer[(ia + 1) * LL + jj]));
            Eb[m] = pack2(__expf(transfer[ia * LL + jj + 64]),
                          __expf(transfer[(ia + 1) * LL + jj + 64]));
        }
    }

    const float* fb[NB];
    const int*   tb[NB];
#pragma unroll
    for (int nb = 0; nb < NB; nb++) {
        fb[nb] = feats  + (size_t)(b0 + nb) * TT * LL;
        tb[nb] = target + (size_t)(b0 + nb) * TT;
    }

    // ---- Gold-path partial sums (emit + trans) ----
    float g[NB];
#pragma unroll
    for (int nb = 0; nb < NB; nb++) {
        float acc = 0.f;
        for (int t = 1 + tid; t < TT; t += 128) {
            const int tg = tb[nb][t];
            const int pr = (t == 1) ? start : tb[nb][t - 1];
            acc += fb[nb][t * LL + tg] + transfer[pr * LL + tg];
        }
        g[nb] = acc;
    }

    // ---- Warm-up: write P(2) for both batches; prime efs pipelines ----
    // P(t) = W(t) * exp(f_t) * 2^-7 ; at iter t we consume P(t), produce P(t+1).
    float efs0[NB], efs1[NB], fraw[NB];
    {
        const float tstart = transfer[start * LL + jown];
#pragma unroll
        for (int nb = 0; nb < NB; nb++) {
            const float W2  = __expf(fb[nb][1 * LL + jown] + tstart); // prev0
            const float ef2 = __expf(fb[nb][2 * LL + jown]) * C128;
            Psh[0][nb][fown] = W2 * ef2;                    // P(2), buf = 2&1 = 0
            efs0[nb] = __expf(fb[nb][3 * LL + jown]) * C128; // for P(3)
            efs1[nb] = __expf(fb[nb][4 * LL + jown]) * C128; // for P(4)
            fraw[nb] = fb[nb][5 * LL + jown];
        }
    }
    __syncthreads();

    const int pbase = ih * 17;   // ulonglong2 base of own i-half in a P row

    // ---- Main scan: 510 iterations; phase-staggered batches ----
    for (int t = 2; t < TT; t++) {
        const int bufr = t & 1;
        const int bufw = bufr ^ 1;
        const int tn   = (t + 4 < TT) ? (t + 4) : (TT - 1);

        // ================= phase 0 : batch 0 =================
        {
            const float fnew = fb[0][tn * LL + jown];       // prefetch (off-path)
            const ulonglong2* P =
                reinterpret_cast<const ulonglong2*>(Psh[bufr][0]) + pbase;
            unsigned long long aA = 0ull, bA = 0ull, aB = 0ull, bB = 0ull;
#pragma unroll
            for (int k = 0; k < 16; k++) {
                const ulonglong2 q = P[k];
                aA = fma2(q.x, Ea[2 * k],     aA);
                bA = fma2(q.y, Ea[2 * k + 1], bA);
                aB = fma2(q.x, Eb[2 * k],     aB);
                bB = fma2(q.y, Eb[2 * k + 1], bB);
            }
            float sA = hsum2(add2(aA, bA));
            float sB = hsum2(add2(aB, bB));
            sA += __shfl_xor_sync(0xffffffffu, sA, 16);
            sB += __shfl_xor_sync(0xffffffffu, sB, 16);
            const float W = ih ? sB : sA;                   // W(t+1)
            Psh[bufw][0][fown] = W * efs0[0];               // P(t+1)
            efs0[0] = efs1[0];
            efs1[0] = __expf(fraw[0]) * C128;               // MUFU hides in BAR
            fraw[0] = fnew;
        }
        __syncthreads();   // BAR_A : P0(t+1) visible; convoy overlapped by dot1 next

        // ================= phase 1 : batch 1 =================
        {
            const float fnew = fb[1][tn * LL + jown];
            const ulonglong2* P =
                reinterpret_cast<const ulonglong2*>(Psh[bufr][1]) + pbase;
            unsigned long long aA = 0ull, bA = 0ull, aB = 0ull, bB = 0ull;
#pragma unroll
            for (int k = 0; k < 16; k++) {
                const ulonglong2 q = P[k];
                aA = fma2(q.x, Ea[2 * k],     aA);
                bA = fma2(q.y, Ea[2 * k + 1], bA);
                aB = fma2(q.x, Eb[2 * k],     aB);
                bB = fma2(q.y, Eb[2 * k + 1], bB);
            }
            float sA = hsum2(add2(aA, bA));
            float sB = hsum2(add2(aB, bB));
            sA += __shfl_xor_sync(0xffffffffu, sA, 16);
            sB += __shfl_xor_sync(0xffffffffu, sB, 16);
            const float W = ih ? sB : sA;
            Psh[bufw][1][fown] = W * efs0[1];
            efs0[1] = efs1[1];
            efs1[1] = __expf(fraw[1]) * C128;
            fraw[1] = fnew;
        }
        __syncthreads();   // BAR_B : P1(t+1) visible; convoy overlapped by dot0 next
    }

    // ---- Final W lives in the last-written buffer's P... recover prev ----
    // After the loop, W(TT) was folded into P(TT) writes (unused garbage) but we
    // still hold W via the last dot: recompute prev from the last stored P is
    // messy — instead read back our own last P(TT) entry and divide out efs?
    // Cleaner: the last useful W is the one computed at t = TT-1 in each phase.
    // We saved it implicitly in the P(TT) store; recover: P(TT) = W * efs_f2.
    // To keep it simple we recompute prev from P(TT) stored in Psh[TT&1].
    float prev[NB];
    {
        // P(TT) = W_final * efs(f_clamped); efs0 currently holds that factor's
        // SUCCESSOR after rotation; we must divide by the factor actually used.
        // We tracked it: at t = TT-1, the store used the then-current efs0,
        // which after rotation became... simplest correct route: recompute the
        // factor from feats directly (f at clamped index TT-1+? ) — the store
        // at t=TT-1 used efs0 == exp(f[tn_last]) ... To avoid fragility, we
        // instead recompute W_final directly: W_final = P_stored / factor_used.
        // factor_used at t=TT-1 was exp(f[min(TT-1+?,...)])*C128 from the
        // pipeline primed with f[3],f[4],f[5]... i.e. factor for P(t+1) is
        // exp(f[t+1 clamped to TT-1])*C128. At t=TT-1: exp(f[TT-1])*C128.
        const int bufl = TT & 1;   // buffer written at t = TT-1
#pragma unroll
        for (int nb = 0; nb < NB; nb++) {
            const float pstored = Psh[bufl][nb][fown];
            const float fac = __expf(fb[nb][(TT - 1) * LL + jown]) * C128;
            const float Wf = pstored / fac;
            prev[nb] = __logf(Wf) + KFINAL;
        }
    }

    const float tstop = transfer[jown * LL + stop];
#pragma unroll
    for (int nb = 0; nb < NB; nb++) {
        const float vv = prev[nb] + tstop;
        float m = vv;
#pragma unroll
        for (int off = 16; off; off >>= 1)
            m = fmaxf(m, __shfl_xor_sync(0xffffffffu, m, off));
        if (lane == 0) smax[nb][wid] = m;
    }
    __syncthreads();
#pragma unroll
    for (int nb = 0; nb < NB; nb++) {
        const float mm = fmaxf(fmaxf(smax[nb][0], smax[nb][1]),
                               fmaxf(smax[nb][2], smax[nb][3]));
        float es = __expf((prev[nb] + tstop) - mm);
        float gg = g[nb];
#pragma unroll
        for (int off = 16; off; off >>= 1) {
            es += __shfl_xor_sync(0xffffffffu, es, off);
            gg += __shfl_xor_sync(0xffffffffu, gg, off);
        }
        if (lane == 0) { ssum[nb][wid] = es; sg[nb][wid] = gg; }
    }
    __syncthreads();

    if (tid < NB) {
        const int nb = tid;
        const float mm = fmaxf(fmaxf(smax[nb][0], smax[nb][1]),
                               fmaxf(smax[nb][2], smax[nb][3]));
        const float Ssum = ssum[nb][0] + ssum[nb][1] + ssum[nb][2] + ssum[nb][3];
        const float sentence = mm + __logf(Ssum);
        const float gsum = sg[nb][0] + sg[nb][1] + sg[nb][2] + sg[nb][3];
        const float emit0 = fb[nb][start];  // feats[b, 0, start]
        out[b0 + nb] = sentence - __expf(emit0 + gsum);
    }
}

extern "C" void kernel_launch(void* const* d_in, const int* in_sizes, int n_in,
                              void* d_out, int out_size) {
    const float* feats    = (const float*)d_in[0];
    const float* transfer = (const float*)d_in[1];
    const int*   target   = (const int*)d_in[2];
    const int*   startp   = (n_in >= 4) ? (const int*)d_in[3] : nullptr;
    const int*   stopp    = (n_in >= 5) ? (const int*)d_in[4] : nullptr;

    crf_kernel<<<NCTA, 128>>>(feats, transfer, target, startp, stopp, (float*)d_out);
}

// round 11
// speedup vs baseline: 1.2648x; 1.2648x over previous
#include <cuda_runtime.h>

// Problem constants (fixed by the dataset): B=512, T=512, L=128
#define BB 512
#define TT 512
#define LL 128
#define NB 2                 // batches per CTA
#define NCTA (BB / NB)       // 256 CTAs, 2 co-resident per SM
#define PROW 136             // padded P row: cols 0-63 at [0,64), 64-127 at [68,132)
#define GROWTH 4.8520303f    // ln(128): expected per-step growth of log-partition

__device__ __forceinline__ unsigned long long pack2(float x, float y) {
    unsigned long long r;
    asm("mov.b64 %0, {%1, %2};" : "=l"(r) : "f"(x), "f"(y));
    return r;
}
__device__ __forceinline__ void unpack2(float& x, float& y, unsigned long long v) {
    asm("mov.b64 {%0, %1}, %2;" : "=f"(x), "=f"(y) : "l"(v));
}
// Packed f32x2 FMA — 2x fp32 throughput on sm_103a.
__device__ __forceinline__ unsigned long long fma2(unsigned long long a,
                                                   unsigned long long b,
                                                   unsigned long long c) {
    unsigned long long d;
    asm("fma.rn.f32x2 %0, %1, %2, %3;" : "=l"(d) : "l"(a), "l"(b), "l"(c));
    return d;
}
__device__ __forceinline__ unsigned long long add2(unsigned long long a,
                                                   unsigned long long b) {
    unsigned long long d;
    asm("add.rn.f32x2 %0, %1, %2;" : "=l"(d) : "l"(a), "l"(b));
    return d;
}
__device__ __forceinline__ float hsum2(unsigned long long v) {
    float x, y;
    unpack2(x, y, v);
    return x + y;
}

// Persistent: one CTA = NB=2 batches, 2 CTAs/SM (independent barrier domains).
// 128 threads. Thread (warp w, lane l):
//   jj = w*16 + (l & 15) : base column in [0,64);  ih = l>>4 : i-half
//   owns columns jj and jj+64 (E regs 2 x 32 f32x2); recurrence col = jj+64*ih.
// Inner dot is SOFTWARE-PIPELINED depth-3: each LDS.128 is issued >= 2 full
// iterations before its FFMA2 consumers, hiding the 29-cycle LDS latency
// structurally (the exposed-scoreboard stall both co-resident CTAs were
// phase-locking on).
__global__ __launch_bounds__(128, 2) void crf_kernel(
    const float* __restrict__ feats,     // [B, T, L]
    const float* __restrict__ transfer,  // [L, L]
    const int*   __restrict__ target,    // [B, T]
    const int*   __restrict__ startp,    // scalar (may be null -> L-2)
    const int*   __restrict__ stopp,     // scalar (may be null -> L-1)
    float*       __restrict__ out)       // [B]
{
    __shared__ __align__(16) float Psh[2][NB][PROW];  // double-buffered padded P
    __shared__ float v0s[2][NB];         // stabilizer anchors
    __shared__ float smax[NB][4];
    __shared__ float ssum[NB][4];
    __shared__ float sg[NB][4];

    const int tid  = threadIdx.x;
    const int lane = tid & 31;
    const int wid  = tid >> 5;
    const int jj   = (wid << 4) + (lane & 15);
    const int ih   = lane >> 4;                 // i-half
    const int jown = jj + (ih << 6);            // recurrence column owned
    const int fown = jj + ih * 68;              // padded float offset of jown
    const int b0   = blockIdx.x * NB;

    const int start = startp ? *startp : (LL - 2);
    const int stop  = stopp  ? *stopp  : (LL - 1);

    // ---- E tiles: i in [64*ih, 64*ih+64) for columns j0=jj and j1=jj+64 ----
    unsigned long long Ea[32], Eb[32];   // Ea: column jj, Eb: column jj+64
    {
        const int i0 = ih << 6;
#pragma unroll
        for (int m = 0; m < 32; m++) {
            const int ia = i0 + 2 * m;
            Ea[m] = pack2(__expf(transfer[ia * LL + jj]),
                          __expf(transfer[(ia + 1) * LL + jj]));
            Eb[m] = pack2(__expf(transfer[ia * LL + jj + 64]),
                          __expf(transfer[(ia + 1) * LL + jj + 64]));
        }
    }

    const float* fb[NB];
    const int*   tb[NB];
#pragma unroll
    for (int nb = 0; nb < NB; nb++) {
        fb[nb] = feats  + (size_t)(b0 + nb) * TT * LL;
        tb[nb] = target + (size_t)(b0 + nb) * TT;
    }

    // ---- Gold-path partial sums (emit + trans), strided over t ----
    float g[NB];
#pragma unroll
    for (int nb = 0; nb < NB; nb++) {
        float acc = 0.f;
        for (int t = 1 + tid; t < TT; t += 128) {
            const int tg = tb[nb][t];
            const int pr = (t == 1) ? start : tb[nb][t - 1];
            acc += fb[nb][t * LL + tg] + transfer[pr * LL + tg];
        }
        g[nb] = acc;
    }

    // ---- Recurrence state for the owned column ----
    float prev[NB], fcur[NB], f1[NB], mhat[NB];
    const float tstart = transfer[start * LL + jown];
#pragma unroll
    for (int nb = 0; nb < NB; nb++) {
        prev[nb] = fb[nb][1 * LL + jown] + tstart;
        fcur[nb] = fb[nb][2 * LL + jown];
        f1[nb]   = fb[nb][3 * LL + jown];
        mhat[nb] = 0.f;
    }

    // LDS base (in ulonglong2) of this thread's i-half within a P row
    const int pbase = ih * 17;

    // ---- Main scan: t = 2 .. T-1 ----
    for (int t = 2; t < TT; t++) {
        const int tn = (t + 2 < TT) ? (t + 2) : (TT - 1);
        float f2[NB], v[NB];
        const int buf = t & 1;
#pragma unroll
        for (int nb = 0; nb < NB; nb++) {
            f2[nb] = fb[nb][tn * LL + jown];           // prefetch, 2 steps ahead
            v[nb]  = prev[nb] + fcur[nb];
            Psh[buf][nb][fown] = __expf(v[nb] - mhat[nb]);
        }
        if (tid == 0) {                                // tid 0 owns column 0
#pragma unroll
            for (int nb = 0; nb < NB; nb++) v0s[buf][nb] = v[nb];
        }
        __syncthreads();

        // Partial dots over own i-half for both columns, both batches.
        // Software-pipelined: 3-slot rotating load buffer per batch; each
        // LDS.128 issued >= 2 iterations before use.
        const ulonglong2* P0 =
            reinterpret_cast<const ulonglong2*>(Psh[buf][0]) + pbase;
        const ulonglong2* P1 =
            reinterpret_cast<const ulonglong2*>(Psh[buf][1]) + pbase;
        unsigned long long aA0 = 0ull, bA0 = 0ull, aB0 = 0ull, bB0 = 0ull;
        unsigned long long aA1 = 0ull, bA1 = 0ull, aB1 = 0ull, bB1 = 0ull;

        ulonglong2 q0a = P0[0], q1a = P1[0];
        ulonglong2 q0b = P0[1], q1b = P1[1];
        ulonglong2 q0c = P0[2], q1c = P1[2];
#pragma unroll
        for (int k = 0; k < 16; k++) {
            const unsigned long long ea0 = Ea[2 * k];
            const unsigned long long ea1 = Ea[2 * k + 1];
            const unsigned long long eb0 = Eb[2 * k];
            const unsigned long long eb1 = Eb[2 * k + 1];
            const ulonglong2 q0 = q0a;
            const ulonglong2 q1 = q1a;
            // rotate and refill (loads land 3 iterations ahead of use)
            q0a = q0b; q0b = q0c;
            q1a = q1b; q1b = q1c;
            if (k + 3 < 16) {
                q0c = P0[k + 3];
                q1c = P1[k + 3];
            }
            aA0 = fma2(q0.x, ea0, aA0);
            bA0 = fma2(q0.y, ea1, bA0);
            aB0 = fma2(q0.x, eb0, aB0);
            bB0 = fma2(q0.y, eb1, bB0);
            aA1 = fma2(q1.x, ea0, aA1);
            bA1 = fma2(q1.y, ea1, bA1);
            aB1 = fma2(q1.x, eb0, aB1);
            bB1 = fma2(q1.y, eb1, bB1);
        }
        float sA0 = hsum2(add2(aA0, bA0));
        float sB0 = hsum2(add2(aB0, bB0));
        float sA1 = hsum2(add2(aA1, bA1));
        float sB1 = hsum2(add2(aB1, bB1));
        sA0 += __shfl_xor_sync(0xffffffffu, sA0, 16);
        sB0 += __shfl_xor_sync(0xffffffffu, sB0, 16);
        sA1 += __shfl_xor_sync(0xffffffffu, sA1, 16);
        sB1 += __shfl_xor_sync(0xffffffffu, sB1, 16);

        const float s0 = ih ? sB0 : sA0;   // full dot for owned column, batch 0
        const float s1 = ih ? sB1 : sA1;   // batch 1

        prev[0] = mhat[0] + __logf(s0);
        prev[1] = mhat[1] + __logf(s1);
#pragma unroll
        for (int nb = 0; nb < NB; nb++) {
            mhat[nb] = v0s[buf][nb] + GROWTH;  // anchor for next step
            fcur[nb] = f1[nb];
            f1[nb]   = f2[nb];
        }
    }

    // ---- Epilogue: sentence scores and gold scores ----
    const float tstop = transfer[jown * LL + stop];
#pragma unroll
    for (int nb = 0; nb < NB; nb++) {
        const float vv = prev[nb] + tstop;
        float m = vv;
#pragma unroll
        for (int off = 16; off; off >>= 1)
            m = fmaxf(m, __shfl_xor_sync(0xffffffffu, m, off));
        if (lane == 0) smax[nb][wid] = m;
    }
    __syncthreads();
#pragma unroll
    for (int nb = 0; nb < NB; nb++) {
        const float mm = fmaxf(fmaxf(smax[nb][0], smax[nb][1]),
                               fmaxf(smax[nb][2], smax[nb][3]));
        float es = __expf((prev[nb] + tstop) - mm);
        float gg = g[nb];
#pragma unroll
        for (int off = 16; off; off >>= 1) {
            es += __shfl_xor_sync(0xffffffffu, es, off);
            gg += __shfl_xor_sync(0xffffffffu, gg, off);
        }
        if (lane == 0) { ssum[nb][wid] = es; sg[nb][wid] = gg; }
    }
    __syncthreads();

    if (tid < NB) {
        const int nb = tid;
        const float mm = fmaxf(fmaxf(smax[nb][0], smax[nb][1]),
                               fmaxf(smax[nb][2], smax[nb][3]));
        const float Ssum = ssum[nb][0] + ssum[nb][1] + ssum[nb][2] + ssum[nb][3];
        const float sentence = mm + __logf(Ssum);
        const float gsum = sg[nb][0] + sg[nb][1] + sg[nb][2] + sg[nb][3];
        const float emit0 = fb[nb][start];  // feats[b, 0, start]
        out[b0 + nb] = sentence - __expf(emit0 + gsum);
    }
}

extern "C" void kernel_launch(void* const* d_in, const int* in_sizes, int n_in,
                              void* d_out, int out_size) {
    const float* feats    = (const float*)d_in[0];
    const float* transfer = (const float*)d_in[1];
    const int*   target   = (const int*)d_in[2];
    const int*   startp   = (n_in >= 4) ? (const int*)d_in[3] : nullptr;
    const int*   stopp    = (n_in >= 5) ? (const int*)d_in[4] : nullptr;

    crf_kernel<<<NCTA, 128>>>(feats, transfer, target, startp, stopp, (float*)d_out);
}

// round 12
// speedup vs baseline: 1.2878x; 1.0182x over previous
#include <cuda_runtime.h>

// Problem constants (fixed by the dataset): B=512, T=512, L=128
#define BB 512
#define TT 512
#define LL 128
#define NB 2                 // batches per CTA
#define NCTA (BB / NB)       // 256 CTAs, 2 co-resident per SM
#define PROW 136             // padded P row: cols 0-63 at [0,64), 64-127 at [68,132)
#define GROWTH 4.8520303f    // ln(128): expected per-step growth of log-partition

__device__ __forceinline__ unsigned long long pack2(float x, float y) {
    unsigned long long r;
    asm("mov.b64 %0, {%1, %2};" : "=l"(r) : "f"(x), "f"(y));
    return r;
}
__device__ __forceinline__ void unpack2(float& x, float& y, unsigned long long v) {
    asm("mov.b64 {%0, %1}, %2;" : "=f"(x), "=f"(y) : "l"(v));
}
// Packed f32x2 FMA — 2x fp32 throughput on sm_103a.
__device__ __forceinline__ unsigned long long fma2(unsigned long long a,
                                                   unsigned long long b,
                                                   unsigned long long c) {
    unsigned long long d;
    asm("fma.rn.f32x2 %0, %1, %2, %3;" : "=l"(d) : "l"(a), "l"(b), "l"(c));
    return d;
}
__device__ __forceinline__ unsigned long long add2(unsigned long long a,
                                                   unsigned long long b) {
    unsigned long long d;
    asm("add.rn.f32x2 %0, %1, %2;" : "=l"(d) : "l"(a), "l"(b));
    return d;
}
__device__ __forceinline__ float hsum2(unsigned long long v) {
    float x, y;
    unpack2(x, y, v);
    return x + y;
}

// Persistent: one CTA = NB=2 batches, 2 CTAs/SM (independent barrier domains).
// 128 threads. Thread (warp w, lane l):
//   jj = w*16 + (l & 15) : base column in [0,64);  ih = l>>4 : i-half
//   owns columns jj and jj+64 (E regs 2 x 32 f32x2); recurrence col = jj+64*ih.
// Inner dot is SOFTWARE-PIPELINED depth-3: each LDS.128 is issued >= 2 full
// iterations before its FFMA2 consumers, hiding the 29-cycle LDS latency
// structurally (the exposed-scoreboard stall both co-resident CTAs were
// phase-locking on).
__global__ __launch_bounds__(128, 2) void crf_kernel(
    const float* __restrict__ feats,     // [B, T, L]
    const float* __restrict__ transfer,  // [L, L]
    const int*   __restrict__ target,    // [B, T]
    const int*   __restrict__ startp,    // scalar (may be null -> L-2)
    const int*   __restrict__ stopp,     // scalar (may be null -> L-1)
    float*       __restrict__ out)       // [B]
{
    __shared__ __align__(16) float Psh[2][NB][PROW];  // double-buffered padded P
    __shared__ float v0s[2][NB];         // stabilizer anchors
    __shared__ float smax[NB][4];
    __shared__ float ssum[NB][4];
    __shared__ float sg[NB][4];

    const int tid  = threadIdx.x;
    const int lane = tid & 31;
    const int wid  = tid >> 5;
    const int jj   = (wid << 4) + (lane & 15);
    const int ih   = lane >> 4;                 // i-half
    const int jown = jj + (ih << 6);            // recurrence column owned
    const int fown = jj + ih * 68;              // padded float offset of jown
    const int b0   = blockIdx.x * NB;

    const int start = startp ? *startp : (LL - 2);
    const int stop  = stopp  ? *stopp  : (LL - 1);

    // ---- E tiles: i in [64*ih, 64*ih+64) for columns j0=jj and j1=jj+64 ----
    unsigned long long Ea[32], Eb[32];   // Ea: column jj, Eb: column jj+64
    {
        const int i0 = ih << 6;
#pragma unroll
        for (int m = 0; m < 32; m++) {
            const int ia = i0 + 2 * m;
            Ea[m] = pack2(__expf(transfer[ia * LL + jj]),
                          __expf(transfer[(ia + 1) * LL + jj]));
            Eb[m] = pack2(__expf(transfer[ia * LL + jj + 64]),
                          __expf(transfer[(ia + 1) * LL + jj + 64]));
        }
    }

    const float* fb[NB];
    const int*   tb[NB];
#pragma unroll
    for (int nb = 0; nb < NB; nb++) {
        fb[nb] = feats  + (size_t)(b0 + nb) * TT * LL;
        tb[nb] = target + (size_t)(b0 + nb) * TT;
    }

    // ---- Gold-path partial sums (emit + trans), strided over t ----
    float g[NB];
#pragma unroll
    for (int nb = 0; nb < NB; nb++) {
        float acc = 0.f;
        for (int t = 1 + tid; t < TT; t += 128) {
            const int tg = tb[nb][t];
            const int pr = (t == 1) ? start : tb[nb][t - 1];
            acc += fb[nb][t * LL + tg] + transfer[pr * LL + tg];
        }
        g[nb] = acc;
    }

    // ---- Recurrence state for the owned column ----
    float prev[NB], fcur[NB], f1[NB], mhat[NB];
    const float tstart = transfer[start * LL + jown];
#pragma unroll
    for (int nb = 0; nb < NB; nb++) {
        prev[nb] = fb[nb][1 * LL + jown] + tstart;
        fcur[nb] = fb[nb][2 * LL + jown];
        f1[nb]   = fb[nb][3 * LL + jown];
        mhat[nb] = 0.f;
    }

    // LDS base (in ulonglong2) of this thread's i-half within a P row
    const int pbase = ih * 17;

    // ---- Main scan: t = 2 .. T-1 ----
    for (int t = 2; t < TT; t++) {
        const int tn = (t + 2 < TT) ? (t + 2) : (TT - 1);
        float f2[NB], v[NB];
        const int buf = t & 1;
#pragma unroll
        for (int nb = 0; nb < NB; nb++) {
            f2[nb] = fb[nb][tn * LL + jown];           // prefetch, 2 steps ahead
            v[nb]  = prev[nb] + fcur[nb];
            Psh[buf][nb][fown] = __expf(v[nb] - mhat[nb]);
        }
        if (tid == 0) {                                // tid 0 owns column 0
#pragma unroll
            for (int nb = 0; nb < NB; nb++) v0s[buf][nb] = v[nb];
        }
        __syncthreads();

        // Partial dots over own i-half for both columns, both batches.
        // Software-pipelined: 3-slot rotating load buffer per batch; each
        // LDS.128 issued >= 2 iterations before use.
        const ulonglong2* P0 =
            reinterpret_cast<const ulonglong2*>(Psh[buf][0]) + pbase;
        const ulonglong2* P1 =
            reinterpret_cast<const ulonglong2*>(Psh[buf][1]) + pbase;
        unsigned long long aA0 = 0ull, bA0 = 0ull, aB0 = 0ull, bB0 = 0ull;
        unsigned long long aA1 = 0ull, bA1 = 0ull, aB1 = 0ull, bB1 = 0ull;

        ulonglong2 q0a = P0[0], q1a = P1[0];
        ulonglong2 q0b = P0[1], q1b = P1[1];
        ulonglong2 q0c = P0[2], q1c = P1[2];
#pragma unroll
        for (int k = 0; k < 16; k++) {
            const unsigned long long ea0 = Ea[2 * k];
            const unsigned long long ea1 = Ea[2 * k + 1];
            const unsigned long long eb0 = Eb[2 * k];
            const unsigned long long eb1 = Eb[2 * k + 1];
            const ulonglong2 q0 = q0a;
            const ulonglong2 q1 = q1a;
            // rotate and refill (loads land 3 iterations ahead of use)
            q0a = q0b; q0b = q0c;
            q1a = q1b; q1b = q1c;
            if (k + 3 < 16) {
                q0c = P0[k + 3];
                q1c = P1[k + 3];
            }
            aA0 = fma2(q0.x, ea0, aA0);
            bA0 = fma2(q0.y, ea1, bA0);
            aB0 = fma2(q0.x, eb0, aB0);
            bB0 = fma2(q0.y, eb1, bB0);
            aA1 = fma2(q1.x, ea0, aA1);
            bA1 = fma2(q1.y, ea1, bA1);
            aB1 = fma2(q1.x, eb0, aB1);
            bB1 = fma2(q1.y, eb1, bB1);
        }
        float sA0 = hsum2(add2(aA0, bA0));
        float sB0 = hsum2(add2(aB0, bB0));
        float sA1 = hsum2(add2(aA1, bA1));
        float sB1 = hsum2(add2(aB1, bB1));
        sA0 += __shfl_xor_sync(0xffffffffu, sA0, 16);
        sB0 += __shfl_xor_sync(0xffffffffu, sB0, 16);
        sA1 += __shfl_xor_sync(0xffffffffu, sA1, 16);
        sB1 += __shfl_xor_sync(0xffffffffu, sB1, 16);

        const float s0 = ih ? sB0 : sA0;   // full dot for owned column, batch 0
        const float s1 = ih ? sB1 : sA1;   // batch 1

        prev[0] = mhat[0] + __logf(s0);
        prev[1] = mhat[1] + __logf(s1);
#pragma unroll
        for (int nb = 0; nb < NB; nb++) {
            mhat[nb] = v0s[buf][nb] + GROWTH;  // anchor for next step
            fcur[nb] = f1[nb];
            f1[nb]   = f2[nb];
        }
    }

    // ---- Epilogue: sentence scores and gold scores ----
    const float tstop = transfer[jown * LL + stop];
#pragma unroll
    for (int nb = 0; nb < NB; nb++) {
        const float vv = prev[nb] + tstop;
        float m = vv;
#pragma unroll
        for (int off = 16; off; off >>= 1)
            m = fmaxf(m, __shfl_xor_sync(0xffffffffu, m, off));
        if (lane == 0) smax[nb][wid] = m;
    }
    __syncthreads();
#pragma unroll
    for (int nb = 0; nb < NB; nb++) {
        const float mm = fmaxf(fmaxf(smax[nb][0], smax[nb][1]),
                               fmaxf(smax[nb][2], smax[nb][3]));
        float es = __expf((prev[nb] + tstop) - mm);
        float gg = g[nb];
#pragma unroll
        for (int off = 16; off; off >>= 1) {
            es += __shfl_xor_sync(0xffffffffu, es, off);
            gg += __shfl_xor_sync(0xffffffffu, gg, off);
        }
        if (lane == 0) { ssum[nb][wid] = es; sg[nb][wid] = gg; }
    }
    __syncthreads();

    if (tid < NB) {
        const int nb = tid;
        const float mm = fmaxf(fmaxf(smax[nb][0], smax[nb][1]),
                               fmaxf(smax[nb][2], smax[nb][3]));
        const float Ssum = ssum[nb][0] + ssum[nb][1] + ssum[nb][2] + ssum[nb][3];
        const float sentence = mm + __logf(Ssum);
        const float gsum = sg[nb][0] + sg[nb][1] + sg[nb][2] + sg[nb][3];
        const float emit0 = fb[nb][start];  // feats[b, 0, start]
        out[b0 + nb] = sentence - __expf(emit0 + gsum);
    }
}

extern "C" void kernel_launch(void* const* d_in, const int* in_sizes, int n_in,
                              void* d_out, int out_size) {
    const float* feats    = (const float*)d_in[0];
    const float* transfer = (const float*)d_in[1];
    const int*   target   = (const int*)d_in[2];
    const int*   startp   = (n_in >= 4) ? (const int*)d_in[3] : nullptr;
    const int*   stopp    = (n_in >= 5) ? (const int*)d_in[4] : nullptr;

    crf_kernel<<<NCTA, 128>>>(feats, transfer, target, startp, stopp, (float*)d_out);
}